// round 1
// baseline (speedup 1.0000x reference)
#include <cuda_runtime.h>
#include <math.h>

#define NB 8
#define CI 128
#define CO 128
#define HH 64
#define WW 64
#define KP 9
#define STAGES 27          // k (9 taps) * b (3 branches), s = k*3 + b
#define CHUNK 16
#define LT 128             // spatial tile (2 rows of 64)
#define NITER (STAGES * (CI / CHUNK))   // 216 k-chunks of 16

// Repacked weights: [stage][c][o], o contiguous for coalesced tile loads.
__device__ __align__(16) float g_Wpk[STAGES * CI * CO];

__global__ void repack_kernel(const float* __restrict__ w0,
                              const float* __restrict__ w1,
                              const float* __restrict__ w2) {
  int idx = blockIdx.x * blockDim.x + threadIdx.x;
  if (idx >= STAGES * CI * CO) return;
  int o = idx & (CO - 1);
  int c = (idx >> 7) & (CI - 1);
  int s = idx >> 14;
  int k = s / 3;
  int b = s - 3 * k;
  const float* w = (b == 0) ? w0 : ((b == 1) ? w1 : w2);
  // w layout: [O][C][3][3] -> flat (o*CI + c)*9 + k
  g_Wpk[idx] = w[(o * CI + c) * KP + k];
}

struct Frag {
  float4 A0, A1;
  float b0[4], b1[4];
  float mk[4];
};

__device__ __forceinline__ void load_frag(
    int iter, const float* __restrict__ xn, int h0, int crow, int l4,
    int brow, int bw, const float (*Msm)[LT], Frag& f) {
  int s  = iter >> 3;
  int c0 = (iter & 7) << 4;
  int k  = s / 3;
  int dy = k / 3 - 1;
  int dx = (k % 3) - 1;

  const float* ap = g_Wpk + (s * CI + c0 + crow) * CO + l4;
  f.A0 = *(const float4*)ap;
  f.A1 = *(const float4*)(ap + CO);

  int  hh  = h0 + brow + dy;
  bool hok = ((unsigned)hh) < HH;
  const float* xp = xn + (c0 + crow) * (HH * WW) + hh * WW + bw + dx;
#pragma unroll
  for (int j = 0; j < 4; ++j) {
    int  wc = bw + dx + j;
    bool ok = hok && (((unsigned)wc) < WW);
    f.b0[j] = ok ? xp[j] : 0.f;
    f.b1[j] = ok ? xp[HH * WW + j] : 0.f;
    f.mk[j] = Msm[s][l4 + j];
  }
}

__device__ __forceinline__ void store_frag(
    int nb, int crow, int l4,
    float (*As)[CHUNK][128], float (*Bs)[CHUNK][128], const Frag& f) {
  *(float4*)&As[nb][crow][l4]     = f.A0;
  *(float4*)&As[nb][crow + 1][l4] = f.A1;
  float4 v0 = make_float4(f.b0[0] * f.mk[0], f.b0[1] * f.mk[1],
                          f.b0[2] * f.mk[2], f.b0[3] * f.mk[3]);
  float4 v1 = make_float4(f.b1[0] * f.mk[0], f.b1[1] * f.mk[1],
                          f.b1[2] * f.mk[2], f.b1[3] * f.mk[3]);
  *(float4*)&Bs[nb][crow][l4]     = v0;
  *(float4*)&Bs[nb][crow + 1][l4] = v1;
}

__global__ __launch_bounds__(256) void conv25d_kernel(
    const float* __restrict__ x, const float* __restrict__ depth,
    const float* __restrict__ fx, float* __restrict__ out) {
  __shared__ __align__(16) float As[2][CHUNK][128];
  __shared__ __align__(16) float Bs[2][CHUNK][128];
  __shared__ float Msm[STAGES][LT];

  const int tid = threadIdx.x;
  const int n   = blockIdx.y;
  const int l0  = blockIdx.x * LT;
  const int h0  = l0 >> 6;

  const float* xn = x + n * CI * HH * WW;
  const float* dn = depth + n * HH * WW;

  // ---- per-tile mask precompute: m_b[k][l] for all 27 stages ----
  if (tid < LT) {
    int l = tid;
    int h = h0 + (l >> 6);
    int w = l & 63;
    float d[9];
#pragma unroll
    for (int kh = 0; kh < 3; ++kh)
#pragma unroll
      for (int kw = 0; kw < 3; ++kw) {
        int  hh2 = h + kh - 1, ww2 = w + kw - 1;
        bool ok  = (((unsigned)hh2) < HH) && (((unsigned)ww2) < WW);
        d[kh * 3 + kw] = ok ? dn[hh2 * WW + ww2] : 0.f;
      }
    float fxn    = fx[n];
    float cvalid = (d[4] != 0.f) ? 1.f : 0.f;
    float center = d[4] * cvalid;
    float grid   = center / fxn;
    float half   = 0.5f * grid;
#pragma unroll
    for (int k = 0; k < 9; ++k) {
      float vld = (d[k] != 0.f) ? cvalid : 0.f;
      float dm  = d[k] * vld;
      float m0  = (fabsf(dm - (center + grid)) <= half) ? 1.f : 0.f;
      float m1  = (fabsf(dm - center) <= half) ? 1.f : 0.f;
      m1 = fminf(m1 + 1.f - vld, 1.f);
      float m2  = (fabsf(dm - (center - grid)) <= half) ? 1.f : 0.f;
      Msm[k * 3 + 0][l] = m0;
      Msm[k * 3 + 1][l] = m1;
      Msm[k * 3 + 2][l] = m2;
    }
  }
  __syncthreads();

  const int lid  = tid & 31;
  const int crow = (tid >> 5) << 1;   // c rows {crow, crow+1} within chunk
  const int l4   = lid << 2;          // 4-wide column group
  const int brow = l4 >> 6;           // 0/1: which of the two image rows
  const int bw   = l4 & 63;
  const int ty   = tid >> 4;          // 0..15 -> o rows
  const int tx   = tid & 15;          // 0..15 -> l cols

  float acc[8][8];
#pragma unroll
  for (int i = 0; i < 8; ++i)
#pragma unroll
    for (int j = 0; j < 8; ++j) acc[i][j] = 0.f;

  Frag f;
  load_frag(0, xn, h0, crow, l4, brow, bw, Msm, f);
  store_frag(0, crow, l4, As, Bs, f);
  __syncthreads();

  int cb = 0;
  for (int iter = 0; iter < NITER; ++iter) {
    Frag fn;
    if (iter + 1 < NITER)
      load_frag(iter + 1, xn, h0, crow, l4, brow, bw, Msm, fn);

#pragma unroll
    for (int cc = 0; cc < CHUNK; ++cc) {
      float4 a0 = *(const float4*)&As[cb][cc][ty * 4];
      float4 a1 = *(const float4*)&As[cb][cc][64 + ty * 4];
      float4 b0 = *(const float4*)&Bs[cb][cc][tx * 4];
      float4 b1 = *(const float4*)&Bs[cb][cc][64 + tx * 4];
      float av[8] = {a0.x, a0.y, a0.z, a0.w, a1.x, a1.y, a1.z, a1.w};
      float bv[8] = {b0.x, b0.y, b0.z, b0.w, b1.x, b1.y, b1.z, b1.w};
#pragma unroll
      for (int i = 0; i < 8; ++i)
#pragma unroll
        for (int j = 0; j < 8; ++j)
          acc[i][j] = fmaf(av[i], bv[j], acc[i][j]);
    }

    if (iter + 1 < NITER) {
      store_frag(cb ^ 1, crow, l4, As, Bs, fn);
      __syncthreads();
      cb ^= 1;
    }
  }

  // ---- epilogue ----
  float* op = out + (size_t)n * CO * HH * WW + l0;
#pragma unroll
  for (int ih = 0; ih < 2; ++ih)
#pragma unroll
    for (int i = 0; i < 4; ++i) {
      int o = ih * 64 + ty * 4 + i;
      int r = ih * 4 + i;
      float4 v0 = make_float4(acc[r][0], acc[r][1], acc[r][2], acc[r][3]);
      float4 v1 = make_float4(acc[r][4], acc[r][5], acc[r][6], acc[r][7]);
      *(float4*)&op[o * (HH * WW) + tx * 4]      = v0;
      *(float4*)&op[o * (HH * WW) + 64 + tx * 4] = v1;
    }
}

extern "C" void kernel_launch(void* const* d_in, const int* in_sizes, int n_in,
                              void* d_out, int out_size) {
  const float* x     = (const float*)d_in[0];
  const float* depth = (const float*)d_in[1];
  const float* fx    = (const float*)d_in[2];
  const float* w0    = (const float*)d_in[3];
  const float* w1    = (const float*)d_in[4];
  const float* w2    = (const float*)d_in[5];
  float* out = (float*)d_out;

  int total = STAGES * CI * CO;
  repack_kernel<<<(total + 255) / 256, 256>>>(w0, w1, w2);

  dim3 grid((HH * WW) / LT, NB);
  conv25d_kernel<<<grid, 256>>>(x, depth, fx, out);
}

// round 3
// speedup vs baseline: 5.4352x; 5.4352x over previous
#include <cuda_runtime.h>
#include <cuda_fp16.h>
#include <cstdint>
#include <math.h>

#define NB 8
#define CI 128
#define CO 128
#define HH 64
#define WW 64
#define LT 128
#define NSTEP 216          // 9 taps * 8 c-chunks(16) * 3 branches, branch innermost
#define BROW 136           // padded B smem row stride in 4B words (conflict-free)

// Fragment-ready fp16 weights: [step][otile(8)][lane(32)][4 regs x 2 halfs]
__device__ __align__(16) __half g_Wh[NSTEP * 2048];

__global__ void repack_kernel(const float* __restrict__ w0,
                              const float* __restrict__ w1,
                              const float* __restrict__ w2) {
  int idx = blockIdx.x * blockDim.x + threadIdx.x;
  if (idx >= NSTEP * 2048) return;
  int e    = idx & 1;
  int r    = (idx >> 1) & 3;
  int lane = (idx >> 3) & 31;
  int t    = (idx >> 8) & 7;
  int step = idx >> 11;
  int b  = step % 3;
  int tc = step / 3;
  int cc = tc & 7, tap = tc >> 3;
  // mma m16n8k16 A-fragment mapping
  int o = t * 16 + (lane >> 2) + 8 * (r & 1);
  int k = 2 * (lane & 3) + 8 * (r >> 1) + e;
  int c = cc * 16 + k;
  const float* w = (b == 0) ? w0 : ((b == 1) ? w1 : w2);
  g_Wh[idx] = __float2half_rn(w[(o * CI + c) * 9 + tap]);
}

__device__ __forceinline__ void mma16816(float* c, const uint32_t* a,
                                         const uint32_t* b) {
  asm volatile(
      "mma.sync.aligned.m16n8k16.row.col.f32.f16.f16.f32 "
      "{%0,%1,%2,%3}, {%4,%5,%6,%7}, {%8,%9}, {%0,%1,%2,%3};"
      : "+f"(c[0]), "+f"(c[1]), "+f"(c[2]), "+f"(c[3])
      : "r"(a[0]), "r"(a[1]), "r"(a[2]), "r"(a[3]), "r"(b[0]), "r"(b[1]));
}

__global__ __launch_bounds__(256, 2) void conv25d_mma(
    const float* __restrict__ x, const float* __restrict__ depth,
    const float* __restrict__ fx, float* __restrict__ out) {
  __shared__ float Msm[27][LT];
  __shared__ __align__(16) uint4 Aw[2][256];          // 2 x 4KB A tiles
  __shared__ __align__(16) uint32_t Bw[2][8 * BROW];  // 2 x padded B tiles

  const int tid = threadIdx.x;
  const int n   = blockIdx.y;
  const int l0  = blockIdx.x * LT;
  const int h0  = l0 >> 6;
  const float* xn = x + (size_t)n * CI * HH * WW;
  const float* dn = depth + (size_t)n * HH * WW;

  // ---- mask precompute: Msm[tap*3+b][l] (verified in round 1) ----
  if (tid < LT) {
    int l = tid, h = h0 + (l >> 6), w = l & 63;
    float d[9];
#pragma unroll
    for (int kh = 0; kh < 3; ++kh)
#pragma unroll
      for (int kw = 0; kw < 3; ++kw) {
        int hh2 = h + kh - 1, ww2 = w + kw - 1;
        bool ok = (((unsigned)hh2) < HH) && (((unsigned)ww2) < WW);
        d[kh * 3 + kw] = ok ? dn[hh2 * WW + ww2] : 0.f;
      }
    float fxn = fx[n];
    float cvalid = (d[4] != 0.f) ? 1.f : 0.f;
    float center = d[4] * cvalid;
    float grid = center / fxn;
    float half = 0.5f * grid;
#pragma unroll
    for (int k = 0; k < 9; ++k) {
      float vld = (d[k] != 0.f) ? cvalid : 0.f;
      float dm = d[k] * vld;
      float m0 = (fabsf(dm - (center + grid)) <= half) ? 1.f : 0.f;
      float m1 = (fabsf(dm - center) <= half) ? 1.f : 0.f;
      m1 = fminf(m1 + 1.f - vld, 1.f);
      float m2 = (fabsf(dm - (center - grid)) <= half) ? 1.f : 0.f;
      Msm[k * 3 + 0][l] = m0;
      Msm[k * 3 + 1][l] = m1;
      Msm[k * 3 + 2][l] = m2;
    }
  }
  __syncthreads();

  // producer mapping: thread -> (c-pair row pc2, 4 consecutive l)
  const int pc2 = tid >> 5;
  const int pl  = (tid & 31) << 2;
  const int ph  = h0 + (pl >> 6);
  const int pw  = pl & 63;

  // consumer mapping: warp -> 64o x 32l tile
  const int lane = tid & 31;
  const int wq = tid >> 5;
  const int oq = wq >> 2, lq = wq & 3;
  const int g = lane >> 2, tig = lane & 3;

  float acc[4][4][4];
#pragma unroll
  for (int i = 0; i < 4; ++i)
#pragma unroll
    for (int j = 0; j < 4; ++j)
#pragma unroll
      for (int r = 0; r < 4; ++r) acc[i][j][r] = 0.f;

  float xr0[4], xr1[4];

  auto produce = [&](int it) {
    int b = it % 3;
    int tc = it / 3;
    int cc = tc & 7, tap = tc >> 3;
    int s = tap * 3 + b;
    if (b == 0) {  // reload x registers once per (tap, c-chunk)
      int dy = tap / 3 - 1, dx = tap % 3 - 1;
      int hh = ph + dy;
      bool okh = ((unsigned)hh) < HH;
      const float* xp = xn + (size_t)(cc * 16 + 2 * pc2) * (HH * WW) +
                        hh * WW + pw + dx;
#pragma unroll
      for (int j = 0; j < 4; ++j) {
        int wwj = pw + dx + j;
        bool ok = okh && (((unsigned)wwj) < WW);
        xr0[j] = ok ? __ldg(xp + j) : 0.f;
        xr1[j] = ok ? __ldg(xp + HH * WW + j) : 0.f;
      }
    }
    int buf = it & 1;
    float4 m = *(const float4*)&Msm[s][pl];
    float mj[4] = {m.x, m.y, m.z, m.w};
    uint32_t v[4];
#pragma unroll
    for (int j = 0; j < 4; ++j) {
      __half2 h2 = __floats2half2_rn(xr0[j] * mj[j], xr1[j] * mj[j]);
      v[j] = *(uint32_t*)&h2;
    }
    *(uint4*)&Bw[buf][pc2 * BROW + pl] = make_uint4(v[0], v[1], v[2], v[3]);
    uint32_t dsta = (uint32_t)__cvta_generic_to_shared(&Aw[buf][tid]);
    const void* srca = (const char*)g_Wh + (size_t)it * 4096 + tid * 16;
    asm volatile("cp.async.cg.shared.global [%0], [%1], 16;" ::"r"(dsta),
                 "l"(srca));
  };

  auto mma_step = [&](int buf) {
    uint32_t a[4][4];
#pragma unroll
    for (int i = 0; i < 4; ++i) {
      uint4 q = Aw[buf][(oq * 4 + i) * 32 + lane];
      a[i][0] = q.x; a[i][1] = q.y; a[i][2] = q.z; a[i][3] = q.w;
    }
    uint32_t bb[4][2];
#pragma unroll
    for (int j = 0; j < 4; ++j) {
      int lcol = lq * 32 + j * 8 + g;
      bb[j][0] = Bw[buf][tig * BROW + lcol];
      bb[j][1] = Bw[buf][(tig + 4) * BROW + lcol];
    }
#pragma unroll
    for (int i = 0; i < 4; ++i)
#pragma unroll
      for (int j = 0; j < 4; ++j) mma16816(acc[i][j], a[i], bb[j]);
  };

  produce(0);
  asm volatile("cp.async.commit_group;");
#pragma unroll 1
  for (int it = 0; it < NSTEP; ++it) {
    if (it + 1 < NSTEP) {
      produce(it + 1);
      asm volatile("cp.async.commit_group;");
      asm volatile("cp.async.wait_group 1;");
    } else {
      asm volatile("cp.async.wait_group 0;");
    }
    __syncthreads();
    mma_step(it & 1);
    __syncthreads();
  }

  // ---- epilogue ----
  float* on = out + (size_t)n * CO * (HH * WW);
#pragma unroll
  for (int i = 0; i < 4; ++i) {
    int obase = oq * 64 + i * 16 + g;
#pragma unroll
    for (int j = 0; j < 4; ++j) {
      int lcol = l0 + lq * 32 + j * 8 + 2 * tig;
      float2 v0 = make_float2(acc[i][j][0], acc[i][j][1]);
      float2 v1 = make_float2(acc[i][j][2], acc[i][j][3]);
      *(float2*)&on[(size_t)obase * (HH * WW) + lcol] = v0;
      *(float2*)&on[(size_t)(obase + 8) * (HH * WW) + lcol] = v1;
    }
  }
}

extern "C" void kernel_launch(void* const* d_in, const int* in_sizes, int n_in,
                              void* d_out, int out_size) {
  const float* x     = (const float*)d_in[0];
  const float* depth = (const float*)d_in[1];
  const float* fx    = (const float*)d_in[2];
  const float* w0    = (const float*)d_in[3];
  const float* w1    = (const float*)d_in[4];
  const float* w2    = (const float*)d_in[5];
  float* out = (float*)d_out;

  repack_kernel<<<(NSTEP * 2048 + 255) / 256, 256>>>(w0, w1, w2);
  dim3 grid((HH * WW) / LT, NB);
  conv25d_mma<<<grid, 256>>>(x, depth, fx, out);
}

// round 4
// speedup vs baseline: 6.4431x; 1.1854x over previous
#include <cuda_runtime.h>
#include <cuda_fp16.h>
#include <cstdint>
#include <math.h>

#define NB 8
#define CI 128
#define CO 128
#define HH 64
#define WW 64
#define HW (HH * WW)
#define LT 128
#define NIT 108            // 9 taps * 4 chunks(32ch) * 3 branches, branch innermost
#define BROW 136           // padded B smem row stride in words
#define NSTG 3             // pipeline stages

#define SM_MSM_B  0                       // 27*128*4 = 13824
#define SM_A_B    13824                   // 3 * 8192
#define SM_B_B    (13824 + 3 * 8192)      // 3 * 8704
#define SM_TOTAL  (13824 + 3 * 8192 + 3 * 8704)   // 64512

// Fragment-ready fp16 weights: [step(108)][khalf(2)][t(8)][lane(32)][r(4)][e(2)]
__device__ __align__(16) __half g_Wh[NIT * 4096];

__global__ void repack_kernel(const float* __restrict__ w0,
                              const float* __restrict__ w1,
                              const float* __restrict__ w2) {
  int idx = blockIdx.x * blockDim.x + threadIdx.x;
  if (idx >= NIT * 4096) return;
  int e    = idx & 1;
  int r    = (idx >> 1) & 3;
  int lane = (idx >> 3) & 31;
  int t    = (idx >> 8) & 7;
  int h    = (idx >> 11) & 1;
  int step = idx >> 12;
  int b  = step % 3;
  int tc = step / 3;
  int ch = tc & 3, tap = tc >> 2;
  int o = t * 16 + (lane >> 2) + 8 * (r & 1);
  int k = 2 * (lane & 3) + 8 * (r >> 1) + e;
  int c = ch * 32 + h * 16 + k;
  const float* w = (b == 0) ? w0 : ((b == 1) ? w1 : w2);
  g_Wh[idx] = __float2half_rn(w[(o * CI + c) * 9 + tap]);
}

__device__ __forceinline__ void mma16816(float* c, const uint32_t* a,
                                         const uint32_t* b) {
  asm volatile(
      "mma.sync.aligned.m16n8k16.row.col.f32.f16.f16.f32 "
      "{%0,%1,%2,%3}, {%4,%5,%6,%7}, {%8,%9}, {%0,%1,%2,%3};"
      : "+f"(c[0]), "+f"(c[1]), "+f"(c[2]), "+f"(c[3])
      : "r"(a[0]), "r"(a[1]), "r"(a[2]), "r"(a[3]), "r"(b[0]), "r"(b[1]));
}

__global__ __launch_bounds__(256, 2) void conv25d_mma(
    const float* __restrict__ x, const float* __restrict__ depth,
    const float* __restrict__ fx, float* __restrict__ out) {
  extern __shared__ __align__(16) char smem[];
  float* Msm = (float*)(smem + SM_MSM_B);          // [27][LT]
  char*  Ab  = smem + SM_A_B;                      // 3 x 8192
  char*  Bb  = smem + SM_B_B;                      // 3 x 8704 (16 rows x BROW words)

  const int tid = threadIdx.x;
  const int n   = blockIdx.y;
  const int l0  = blockIdx.x * LT;
  const int h0  = l0 >> 6;
  const float* xn = x + (size_t)n * CI * HW;
  const float* dn = depth + (size_t)n * HW;

  // ---- mask precompute (verified) ----
  if (tid < LT) {
    int l = tid, h = h0 + (l >> 6), w = l & 63;
    float d[9];
#pragma unroll
    for (int kh = 0; kh < 3; ++kh)
#pragma unroll
      for (int kw = 0; kw < 3; ++kw) {
        int hh2 = h + kh - 1, ww2 = w + kw - 1;
        bool ok = (((unsigned)hh2) < HH) && (((unsigned)ww2) < WW);
        d[kh * 3 + kw] = ok ? dn[hh2 * WW + ww2] : 0.f;
      }
    float fxn = fx[n];
    float cvalid = (d[4] != 0.f) ? 1.f : 0.f;
    float center = d[4] * cvalid;
    float grid = center / fxn;
    float half = 0.5f * grid;
#pragma unroll
    for (int k = 0; k < 9; ++k) {
      float vld = (d[k] != 0.f) ? cvalid : 0.f;
      float dm = d[k] * vld;
      float m0 = (fabsf(dm - (center + grid)) <= half) ? 1.f : 0.f;
      float m1 = (fabsf(dm - center) <= half) ? 1.f : 0.f;
      m1 = fminf(m1 + 1.f - vld, 1.f);
      float m2 = (fabsf(dm - (center - grid)) <= half) ? 1.f : 0.f;
      Msm[(k * 3 + 0) * LT + l] = m0;
      Msm[(k * 3 + 1) * LT + l] = m1;
      Msm[(k * 3 + 2) * LT + l] = m2;
    }
  }
  __syncthreads();

  // producer mapping
  const int pc2 = tid >> 5;            // c-pair row within 16-ch half
  const int pl  = (tid & 31) << 2;     // 4 consecutive l
  const int ph  = h0 + (pl >> 6);
  const int pw  = pl & 63;

  // consumer mapping: warp -> 64o x 32l
  const int lane = tid & 31;
  const int wq = tid >> 5;
  const int oq = wq >> 2, lq = wq & 3;
  const int g = lane >> 2, tig = lane & 3;

  float acc[4][4][4];
#pragma unroll
  for (int i = 0; i < 4; ++i)
#pragma unroll
    for (int j = 0; j < 4; ++j)
#pragma unroll
      for (int r = 0; r < 4; ++r) acc[i][j][r] = 0.f;

  float xr[2][2][4];

  auto produce = [&](int it) {
    int b = it % 3;
    int tc = it / 3;
    int ch = tc & 3, tap = tc >> 2;
    int s = tap * 3 + b;
    int stg = it % NSTG;
    // A tile via cp.async (8KB)
    {
      uint32_t dsta =
          (uint32_t)__cvta_generic_to_shared(Ab + stg * 8192 + tid * 16);
      const char* srca = (const char*)g_Wh + (size_t)it * 8192 + tid * 16;
      asm volatile("cp.async.cg.shared.global [%0], [%1], 16;" ::"r"(dsta),
                   "l"(srca));
      asm volatile("cp.async.cg.shared.global [%0], [%1], 16;" ::"r"(
                       dsta + 4096),
                   "l"(srca + 4096));
    }
    if (b == 0) {  // load x regs once per (tap, chunk32)
      int dy = tap / 3 - 1, dx = tap % 3 - 1;
      int hh = ph + dy;
      bool okh = ((unsigned)hh) < HH;
      const float* base = xn + hh * WW + pw + dx;
#pragma unroll
      for (int h = 0; h < 2; ++h)
#pragma unroll
        for (int e = 0; e < 2; ++e) {
          const float* xp = base + (size_t)(ch * 32 + h * 16 + 2 * pc2 + e) * HW;
#pragma unroll
          for (int j = 0; j < 4; ++j) {
            bool ok = okh && (((unsigned)(pw + dx + j)) < WW);
            xr[h][e][j] = ok ? __ldg(xp + j) : 0.f;
          }
        }
    }
    float4 m = *(const float4*)&Msm[s * LT + pl];
    float mj[4] = {m.x, m.y, m.z, m.w};
    uint32_t* bp = (uint32_t*)(Bb + stg * 8704);
#pragma unroll
    for (int h = 0; h < 2; ++h) {
      uint32_t v[4];
#pragma unroll
      for (int j = 0; j < 4; ++j) {
        __half2 h2 = __floats2half2_rn(xr[h][0][j] * mj[j], xr[h][1][j] * mj[j]);
        v[j] = *(uint32_t*)&h2;
      }
      *(uint4*)&bp[(h * 8 + pc2) * BROW + pl] = make_uint4(v[0], v[1], v[2], v[3]);
    }
    asm volatile("cp.async.commit_group;");
  };

  auto mma_step = [&](int stg) {
    const uint4* ap = (const uint4*)(Ab + stg * 8192);
    const uint32_t* bp = (const uint32_t*)(Bb + stg * 8704);
#pragma unroll
    for (int h = 0; h < 2; ++h) {
      uint32_t a[4][4];
#pragma unroll
      for (int i = 0; i < 4; ++i) {
        uint4 q = ap[h * 256 + (oq * 4 + i) * 32 + lane];
        a[i][0] = q.x; a[i][1] = q.y; a[i][2] = q.z; a[i][3] = q.w;
      }
      uint32_t bb[4][2];
#pragma unroll
      for (int j = 0; j < 4; ++j) {
        int lcol = lq * 32 + j * 8 + g;
        bb[j][0] = bp[(h * 8 + tig) * BROW + lcol];
        bb[j][1] = bp[(h * 8 + tig + 4) * BROW + lcol];
      }
#pragma unroll
      for (int i = 0; i < 4; ++i)
#pragma unroll
        for (int j = 0; j < 4; ++j) mma16816(acc[i][j], a[i], bb[j]);
    }
  };

  produce(0);
  produce(1);
#pragma unroll 1
  for (int it = 0; it < NIT; ++it) {
    asm volatile("cp.async.wait_group 1;");
    __syncthreads();
    mma_step(it % NSTG);
    if (it + 2 < NIT) produce(it + 2);
  }

  // ---- epilogue ----
  float* on = out + (size_t)n * CO * HW;
#pragma unroll
  for (int i = 0; i < 4; ++i) {
    int obase = oq * 64 + i * 16 + g;
#pragma unroll
    for (int j = 0; j < 4; ++j) {
      int lcol = l0 + lq * 32 + j * 8 + 2 * tig;
      float2 v0 = make_float2(acc[i][j][0], acc[i][j][1]);
      float2 v1 = make_float2(acc[i][j][2], acc[i][j][3]);
      *(float2*)&on[(size_t)obase * HW + lcol] = v0;
      *(float2*)&on[(size_t)(obase + 8) * HW + lcol] = v1;
    }
  }
}

extern "C" void kernel_launch(void* const* d_in, const int* in_sizes, int n_in,
                              void* d_out, int out_size) {
  const float* x     = (const float*)d_in[0];
  const float* depth = (const float*)d_in[1];
  const float* fx    = (const float*)d_in[2];
  const float* w0    = (const float*)d_in[3];
  const float* w1    = (const float*)d_in[4];
  const float* w2    = (const float*)d_in[5];
  float* out = (float*)d_out;

  cudaFuncSetAttribute(conv25d_mma,
                       cudaFuncAttributeMaxDynamicSharedMemorySize, SM_TOTAL);

  repack_kernel<<<(NIT * 4096 + 255) / 256, 256>>>(w0, w1, w2);
  dim3 grid((HH * WW) / LT, NB);
  conv25d_mma<<<grid, 256, SM_TOTAL>>>(x, depth, fx, out);
}